// round 9
// baseline (speedup 1.0000x reference)
#include <cuda_runtime.h>
#include <cuda_bf16.h>
#include <cstdint>

// Problem constants (fixed by the dataset).
#define TREES 64
#define DNODES 255      // internal nodes per tree (2^8 - 1)
#define KLEAF 256       // leaves per tree
#define MFEAT 512       // features
#define CCLS 8          // classes
#define BATCH 4096

// Blocking: lane = batch row. CTA = 256 threads (8 warps) x 32 rows.
// Warp w owns leaves [32w, 32w+32) of each tree; CTA covers TGROUP trees.
#define ROWS 32
#define TGROUP 8        // trees per CTA (gridDim.y = TREES/TGROUP = 8 -> 1024 CTAs)
#define XSTRIDE 513     // padded row stride: bank(lane*513+f) = (lane+f)%32 -> conflict-free

// Scratch (no cudaMalloc allowed): packed per-node parameters.
// g_node[t*DNODES+d] = { __int_as_float(feature_index), 5*b1 }.
__device__ float2 g_node[TREES * DNODES];

// ---------------------------------------------------------------------------
// Preprocess: extract one-hot feature index from W1 rows; pack with 5*b1.
// One warp per (t,d) row of 512 floats.
// ---------------------------------------------------------------------------
__global__ void prep_kernel(const float* __restrict__ W1,
                            const float* __restrict__ b1)
{
    int row = blockIdx.x * (blockDim.x >> 5) + (threadIdx.x >> 5);
    if (row >= TREES * DNODES) return;
    int lane = threadIdx.x & 31;

    const float4* w4 = reinterpret_cast<const float4*>(W1 + (size_t)row * MFEAT);
    int idx = 0;
#pragma unroll
    for (int i = 0; i < 4; i++) {
        float4 v = w4[i * 32 + lane];
        int base = (i * 32 + lane) * 4;
        if (v.x != 0.0f) idx = base + 0;
        if (v.y != 0.0f) idx = base + 1;
        if (v.z != 0.0f) idx = base + 2;
        if (v.w != 0.0f) idx = base + 3;
    }
#pragma unroll
    for (int off = 16; off; off >>= 1)
        idx = max(idx, __shfl_xor_sync(0xffffffffu, idx, off));
    if (lane == 0) {
        // sigmoid(10x+10b) = 0.5 + 0.5*tanh(5x+5b)
        g_node[row] = make_float2(__int_as_float(idx), 5.0f * b1[row]);
    }
}

// th = tanh(z) via single MUFU.TANH.
__device__ __forceinline__ float tanhf_hw(float z)
{
    float r;
    asm("tanh.approx.f32 %0, %1;" : "=f"(r) : "f"(z));
    return r;
}

// Pack two floats into a 64-bit register pair.
__device__ __forceinline__ unsigned long long pk2(float lo, float hi)
{
    unsigned long long r;
    asm("mov.b64 %0, {%1, %2};" : "=l"(r) : "f"(lo), "f"(hi));
    return r;
}
// Packed dual FFMA (Blackwell FFMA2, PTX-only).
__device__ __forceinline__ unsigned long long ffma2(unsigned long long a,
                                                    unsigned long long b,
                                                    unsigned long long c)
{
    unsigned long long d;
    asm("fma.rn.f32x2 %0, %1, %2, %3;" : "=l"(d) : "l"(a), "l"(b), "l"(c));
    return d;
}
__device__ __forceinline__ void upk2(unsigned long long v, float& lo, float& hi)
{
    asm("mov.b64 {%0, %1}, %2;" : "=f"(lo), "=f"(hi) : "l"(v));
}

// ---------------------------------------------------------------------------
// Main kernel, row-per-lane layout:
//  - lane owns batch row (bbase+lane): x gathers hit xs[lane*513+f], banks
//    (lane+f)%32 -> conflict-free; node params are warp-uniform LDS
//    broadcasts (1 wavefront); Cw is read with warp-UNIFORM LDG.128 straight
//    from L2 (no smem stage -> smem ~67.8 KB -> 3 CTAs/SM).
//  - warp w owns leaves [32w,32w+32): path nodes (levels 0..3, last = 7+w)
//    then the 30-node subtree below; 34 tanh per lane-tree.
//  - no shfls, no cross-lane reduction: lane's acc covers its own row.
// ---------------------------------------------------------------------------
__global__ __launch_bounds__(256, 3)
void forest_kernel(const float* __restrict__ x,
                   const float* __restrict__ Cw,
                   float* __restrict__ out)
{
    extern __shared__ float smem[];
    float*  xs   = smem;                                            // 32*513 floats
    float2* ndsh = reinterpret_cast<float2*>(smem + ROWS * XSTRIDE); // 255 float2

    const int tid   = threadIdx.x;
    const int lane  = tid & 31;
    const int w     = tid >> 5;                  // warp id = leaf slice
    const int bbase = blockIdx.x * ROWS;
    const int tbase = blockIdx.y * TGROUP;

    // Stage 32 x-rows into padded smem (coalesced LDG.128, scalar STS).
    {
        const float4* xg4 = reinterpret_cast<const float4*>(x + (size_t)bbase * MFEAT);
#pragma unroll
        for (int i = 0; i < (ROWS * MFEAT / 4) / 256; i++) {   // 16 iters
            int idx4 = i * 256 + tid;
            float4 v = xg4[idx4];
            int row = idx4 >> 7;              // 128 float4 per row
            int f   = (idx4 & 127) * 4;
            float* d = xs + row * XSTRIDE + f;
            d[0] = v.x; d[1] = v.y; d[2] = v.z; d[3] = v.w;
        }
    }

    // Warp-constant path node ids / signs (levels 0..2), level-3 node = 7+w.
    const float sg0 = (w & 4) ? 0.5f : -0.5f;
    const float sg1 = (w & 2) ? 0.5f : -0.5f;
    const float sg2 = (w & 1) ? 0.5f : -0.5f;
    const int a1 = 1 + (w >> 2);
    const int a2 = 3 + (w >> 1);
    const int a3 = 7 + w;

    const float* xr = xs + lane * XSTRIDE;       // this lane's row

    unsigned long long acc2[4] = {0ull, 0ull, 0ull, 0ull};

#pragma unroll 1
    for (int tt = 0; tt < TGROUP; tt++) {
        const int t = tbase + tt;
        __syncthreads();   // x staged / previous tree's tables no longer read

        // Stage per-tree node table (uniform-broadcast consumers).
        for (int i = tid; i < DNODES; i += 256)
            ndsh[i] = g_node[t * DNODES + i];
        __syncthreads();

        // Node evaluator: broadcast LDS of params, conflict-free gather, tanh.
        auto nodeth = [&](int n) -> float {
            float2 nv = ndsh[n];
            return tanhf_hw(fmaf(5.0f, xr[__float_as_int(nv.x)], nv.y));
        };

        // Path levels 0..3.
        float th0 = nodeth(0);
        float th1 = nodeth(a1);
        float th2 = nodeth(a2);
        float th3 = nodeth(a3);
        float pre = fmaf(sg0, th0, 0.5f) * fmaf(sg1, th1, 0.5f) * fmaf(sg2, th2, 0.5f);
        float pA = pre * fmaf(-0.5f, th3, 0.5f);
        float pB = pre * fmaf( 0.5f, th3, 0.5f);

        // Level 4 (2 nodes) -> q[4].
        float q[4];
        {
            float t4a = nodeth(15 + 2 * w);
            float t4b = nodeth(16 + 2 * w);
            q[0] = pA * fmaf(-0.5f, t4a, 0.5f); q[1] = pA * fmaf(0.5f, t4a, 0.5f);
            q[2] = pB * fmaf(-0.5f, t4b, 0.5f); q[3] = pB * fmaf(0.5f, t4b, 0.5f);
        }
        // Level 5 (4 nodes) -> r[8].
        float r[8];
#pragma unroll
        for (int i = 0; i < 4; i++) {
            float th = nodeth(31 + 4 * w + i);
            r[2 * i]     = q[i] * fmaf(-0.5f, th, 0.5f);
            r[2 * i + 1] = q[i] * fmaf( 0.5f, th, 0.5f);
        }
        // Level 6 (8 nodes) -> u[16].
        float u[16];
#pragma unroll
        for (int i = 0; i < 8; i++) {
            float th = nodeth(63 + 8 * w + i);
            u[2 * i]     = r[i] * fmaf(-0.5f, th, 0.5f);
            u[2 * i + 1] = r[i] * fmaf( 0.5f, th, 0.5f);
        }

        // Level 7 (16 nodes): 32 leaves, contract with warp-uniform LDG of Cw.
        const ulonglong2* cwp = reinterpret_cast<const ulonglong2*>(
            Cw + (size_t)t * (KLEAF * CCLS)) + (size_t)w * 64;
#pragma unroll
        for (int i = 0; i < 16; i++) {
            float th = nodeth(127 + 16 * w + i);
            float P0 = u[i] * fmaf(-0.5f, th, 0.5f);
            float P1 = u[i] * fmaf( 0.5f, th, 0.5f);
            // leaf (2i): classes 0..3, 4..7 ; leaf (2i+1) likewise.
            ulonglong2 cA0 = __ldg(&cwp[4 * i + 0]);
            ulonglong2 cA1 = __ldg(&cwp[4 * i + 1]);
            ulonglong2 cB0 = __ldg(&cwp[4 * i + 2]);
            ulonglong2 cB1 = __ldg(&cwp[4 * i + 3]);
            unsigned long long pp0 = pk2(P0, P0);
            unsigned long long pp1 = pk2(P1, P1);
            acc2[0] = ffma2(pp0, cA0.x, acc2[0]);
            acc2[1] = ffma2(pp0, cA0.y, acc2[1]);
            acc2[2] = ffma2(pp0, cA1.x, acc2[2]);
            acc2[3] = ffma2(pp0, cA1.y, acc2[3]);
            acc2[0] = ffma2(pp1, cB0.x, acc2[0]);
            acc2[1] = ffma2(pp1, cB0.y, acc2[1]);
            acc2[2] = ffma2(pp1, cB1.x, acc2[2]);
            acc2[3] = ffma2(pp1, cB1.y, acc2[3]);
        }
    }

    // Lane owns row bbase+lane entirely for its leaf slice: scale and
    // atomically add (8 slices x 8 tree-groups accumulate per element).
    const float inv_t = 1.0f / (float)TREES;
    float a[CCLS];
#pragma unroll
    for (int qq = 0; qq < 4; qq++)
        upk2(acc2[qq], a[2 * qq], a[2 * qq + 1]);
    float* orow = out + (size_t)(bbase + lane) * CCLS;
#pragma unroll
    for (int c = 0; c < CCLS; c++)
        atomicAdd(&orow[c], a[c] * inv_t);
}

// ---------------------------------------------------------------------------
extern "C" void kernel_launch(void* const* d_in, const int* in_sizes, int n_in,
                              void* d_out, int out_size)
{
    // Identify inputs by element count (order per metadata: input, W1, b1,
    // Bpos, Bneg, Cw — Bpos/Bneg are structurally fixed and unused).
    const float* x  = nullptr;
    const float* W1 = nullptr;
    const float* b1 = nullptr;
    const float* Cw = nullptr;
    for (int i = 0; i < n_in; i++) {
        switch (in_sizes[i]) {
            case BATCH * MFEAT:          x  = (const float*)d_in[i]; break; // 2097152
            case TREES * DNODES * MFEAT: W1 = (const float*)d_in[i]; break; // 8355840
            case TREES * DNODES:         b1 = (const float*)d_in[i]; break; // 16320
            case TREES * KLEAF * CCLS:   Cw = (const float*)d_in[i]; break; // 131072
            default: break;                                                 // Bpos/Bneg
        }
    }
    float* out = (float*)d_out;

    static const size_t smem_bytes =
        (size_t)(ROWS * XSTRIDE) * 4 + (size_t)DNODES * 8;   // ~67.7 KB
    cudaFuncSetAttribute(forest_kernel,
                         cudaFuncAttributeMaxDynamicSharedMemorySize,
                         (int)smem_bytes);

    cudaMemsetAsync(d_out, 0, (size_t)out_size * sizeof(float), 0);

    {
        int rows = TREES * DNODES;
        int warps_per_block = 8;
        int blocks = (rows + warps_per_block - 1) / warps_per_block;
        prep_kernel<<<blocks, warps_per_block * 32>>>(W1, b1);
    }

    dim3 grid(BATCH / ROWS, TREES / TGROUP);   // (128, 8) = 1024 CTAs
    forest_kernel<<<grid, 256, smem_bytes>>>(x, Cw, out);
}

// round 10
// speedup vs baseline: 1.4260x; 1.4260x over previous
#include <cuda_runtime.h>
#include <cuda_bf16.h>
#include <cstdint>

// Problem constants (fixed by the dataset).
#define TREES 64
#define DNODES 255      // internal nodes per tree (2^8 - 1)
#define KLEAF 256       // leaves per tree
#define MFEAT 512       // features
#define CCLS 8          // classes
#define BATCH 4096

// Blocking: CTA = 512 threads (16 warps) over 64 batch rows x 16 trees.
// Lane L owns rows (bbase+L, bbase+L+32) -> f32x2-packed math.
// Warp: slice s = w&7 (leaves [32s,32s+32)), tree half h = w>>3.
#define ROWS 64
#define TGROUP 16       // trees per CTA, split 8/8 across halves
#define XSTRIDE 513     // bank(L*513+f) = (L+f)%32 and (L+32)*513+f same set -> conflict-free

// Scratch (no cudaMalloc allowed): packed per-node parameters.
// g_node[t*DNODES+d] = { __int_as_float(feature_index), 5*b1 }.
__device__ float2 g_node[TREES * DNODES];

// ---------------------------------------------------------------------------
// Preprocess: extract one-hot feature index from W1 rows; pack with 5*b1.
// One warp per (t,d) row of 512 floats.
// ---------------------------------------------------------------------------
__global__ void prep_kernel(const float* __restrict__ W1,
                            const float* __restrict__ b1)
{
    int row = blockIdx.x * (blockDim.x >> 5) + (threadIdx.x >> 5);
    if (row >= TREES * DNODES) return;
    int lane = threadIdx.x & 31;

    const float4* w4 = reinterpret_cast<const float4*>(W1 + (size_t)row * MFEAT);
    int idx = 0;
#pragma unroll
    for (int i = 0; i < 4; i++) {
        float4 v = w4[i * 32 + lane];
        int base = (i * 32 + lane) * 4;
        if (v.x != 0.0f) idx = base + 0;
        if (v.y != 0.0f) idx = base + 1;
        if (v.z != 0.0f) idx = base + 2;
        if (v.w != 0.0f) idx = base + 3;
    }
#pragma unroll
    for (int off = 16; off; off >>= 1)
        idx = max(idx, __shfl_xor_sync(0xffffffffu, idx, off));
    if (lane == 0) {
        // sigmoid(10x+10b) = 0.5 + 0.5*tanh(5x+5b)
        g_node[row] = make_float2(__int_as_float(idx), 5.0f * b1[row]);
    }
}

// th = tanh(z) via single MUFU.TANH.
__device__ __forceinline__ float tanhf_hw(float z)
{
    float r;
    asm("tanh.approx.f32 %0, %1;" : "=f"(r) : "f"(z));
    return r;
}

typedef unsigned long long ull;

__device__ __forceinline__ ull pk2(float lo, float hi)
{
    ull r;
    asm("mov.b64 %0, {%1, %2};" : "=l"(r) : "f"(lo), "f"(hi));
    return r;
}
__device__ __forceinline__ ull ffma2(ull a, ull b, ull c)
{
    ull d;
    asm("fma.rn.f32x2 %0, %1, %2, %3;" : "=l"(d) : "l"(a), "l"(b), "l"(c));
    return d;
}
__device__ __forceinline__ ull mul2(ull a, ull b)
{
    ull d;
    asm("mul.rn.f32x2 %0, %1, %2;" : "=l"(d) : "l"(a), "l"(b));
    return d;
}
__device__ __forceinline__ void upk2(ull v, float& lo, float& hi)
{
    asm("mov.b64 {%0, %1}, %2;" : "=f"(lo), "=f"(hi) : "l"(v));
}

#define H2  0x3F0000003F000000ull   // {0.5f, 0.5f}
#define NH2 0xBF000000BF000000ull   // {-0.5f, -0.5f}

// ---------------------------------------------------------------------------
// Main kernel. 512 threads, 64 rows staged (row-major, stride 513), two tree
// halves run concurrently on disjoint warp sets with double-buffered nd/Cw
// smem tables. Per warp-tree, nd broadcasts + Cw uniform LDS amortize over 64
// rows (2 per lane) instead of 32 -> 37% less L1tex work per result. All
// tree-product arithmetic packed f32x2 over the row pair.
// ---------------------------------------------------------------------------
__global__ __launch_bounds__(512, 1)
void forest_kernel(const float* __restrict__ x,
                   const float* __restrict__ Cw,
                   float* __restrict__ out)
{
    extern __shared__ float smem[];
    float*  xs   = smem;                                            // 64*513 floats
    float2* ndsh = reinterpret_cast<float2*>(smem + ROWS * XSTRIDE); // 2*256 float2
    float4* cwsh = reinterpret_cast<float4*>(smem + ROWS * XSTRIDE + 1024); // 2*512 float4

    const int tid   = threadIdx.x;
    const int lane  = tid & 31;
    const int w     = tid >> 5;
    const int s     = w & 7;          // leaf slice
    const int h     = w >> 3;         // tree half
    const int bbase = blockIdx.x * ROWS;
    const int tbase = blockIdx.y * TGROUP;

    // Stage 64 x-rows (coalesced LDG.128; scalar STS, 4-way bank conflicts
    // acceptable for a one-time stage).
    {
        const float4* xg4 = reinterpret_cast<const float4*>(x + (size_t)bbase * MFEAT);
#pragma unroll
        for (int i = 0; i < (ROWS * MFEAT / 4) / 512; i++) {   // 16 iters
            int idx4 = i * 512 + tid;
            float4 v = xg4[idx4];
            int row = idx4 >> 7;              // 128 float4 per row
            int f   = (idx4 & 127) * 4;
            float* d = xs + row * XSTRIDE + f;
            d[0] = v.x; d[1] = v.y; d[2] = v.z; d[3] = v.w;
        }
    }

    // Warp-constant path node ids / sign splats (levels 0..2); level-3 = 7+s.
    const ull sg0 = (s & 4) ? H2 : NH2;
    const ull sg1 = (s & 2) ? H2 : NH2;
    const ull sg2 = (s & 1) ? H2 : NH2;
    const int a1 = 1 + (s >> 2);
    const int a2 = 3 + (s >> 1);
    const int a3 = 7 + s;

    const float* xrA = xs + lane * XSTRIDE;           // row bbase+lane
    const float* xrB = xs + (lane + 32) * XSTRIDE;    // row bbase+lane+32
    const float2* ndh = ndsh + h * 256;
    const float4* cwh = cwsh + h * 512;

    ull accA[4] = {0, 0, 0, 0};
    ull accB[4] = {0, 0, 0, 0};

    // Staging half for this thread (256 threads per half).
    const int hs = tid >> 8;
    const int st = tid & 255;

#pragma unroll 1
    for (int tt = 0; tt < TGROUP / 2; tt++) {
        __syncthreads();   // xs staged / previous iteration's tables released

        // Stage both halves' nd + Cw tables for this iteration's trees.
        {
            const int t_st = tbase + hs * (TGROUP / 2) + tt;
            const float2* gsrc = g_node + (size_t)t_st * DNODES;
            float2* nddst = ndsh + hs * 256;
            if (st < DNODES) nddst[st] = gsrc[st];
            const float4* cws = reinterpret_cast<const float4*>(
                Cw + (size_t)t_st * (KLEAF * CCLS));
            float4* cwd = cwsh + hs * 512;
            cwd[st]       = cws[st];
            cwd[st + 256] = cws[st + 256];
        }
        __syncthreads();

        // Node evaluator: broadcast LDS of params, 2 conflict-free gathers,
        // 2 tanh, pack rows as f32x2.
        auto nodeth2 = [&](int n) -> ull {
            float2 nv = ndh[n];
            int f = __float_as_int(nv.x);
            float tA = tanhf_hw(fmaf(5.0f, xrA[f], nv.y));
            float tB = tanhf_hw(fmaf(5.0f, xrB[f], nv.y));
            return pk2(tA, tB);
        };

        // Path levels 0..3.
        ull th0 = nodeth2(0);
        ull th1 = nodeth2(a1);
        ull th2 = nodeth2(a2);
        ull th3 = nodeth2(a3);
        ull pre = mul2(mul2(ffma2(sg0, th0, H2), ffma2(sg1, th1, H2)),
                       ffma2(sg2, th2, H2));
        ull pA = mul2(pre, ffma2(NH2, th3, H2));
        ull pB = mul2(pre, ffma2(H2,  th3, H2));

        // Level 4 (2 nodes) -> q[4].
        ull q[4];
        {
            ull t4a = nodeth2(15 + 2 * s);
            ull t4b = nodeth2(16 + 2 * s);
            q[0] = mul2(pA, ffma2(NH2, t4a, H2)); q[1] = mul2(pA, ffma2(H2, t4a, H2));
            q[2] = mul2(pB, ffma2(NH2, t4b, H2)); q[3] = mul2(pB, ffma2(H2, t4b, H2));
        }
        // Level 5 (4 nodes) -> r[8].
        ull r[8];
#pragma unroll
        for (int i = 0; i < 4; i++) {
            ull th = nodeth2(31 + 4 * s + i);
            r[2 * i]     = mul2(q[i], ffma2(NH2, th, H2));
            r[2 * i + 1] = mul2(q[i], ffma2(H2,  th, H2));
        }
        // Level 6 (8 nodes) -> u[16].
        ull u[16];
#pragma unroll
        for (int i = 0; i < 8; i++) {
            ull th = nodeth2(63 + 8 * s + i);
            u[2 * i]     = mul2(r[i], ffma2(NH2, th, H2));
            u[2 * i + 1] = mul2(r[i], ffma2(H2,  th, H2));
        }

        // Level 7 (16 nodes): 32 leaves, contract with uniform LDS of Cw.
        const ulonglong2* cwp = reinterpret_cast<const ulonglong2*>(cwh) + (size_t)s * 64;
#pragma unroll
        for (int i = 0; i < 16; i++) {
            ull th = nodeth2(127 + 16 * s + i);
            ull P0 = mul2(u[i], ffma2(NH2, th, H2));
            ull P1 = mul2(u[i], ffma2(H2,  th, H2));
            float P0A, P0B, P1A, P1B;
            upk2(P0, P0A, P0B);
            upk2(P1, P1A, P1B);
            ulonglong2 cA0 = cwp[4 * i + 0];   // leaf 2i  : classes 0..3
            ulonglong2 cA1 = cwp[4 * i + 1];   // leaf 2i  : classes 4..7
            ulonglong2 cB0 = cwp[4 * i + 2];   // leaf 2i+1: classes 0..3
            ulonglong2 cB1 = cwp[4 * i + 3];   // leaf 2i+1: classes 4..7
            ull pp0A = pk2(P0A, P0A), pp1A = pk2(P1A, P1A);
            ull pp0B = pk2(P0B, P0B), pp1B = pk2(P1B, P1B);
            accA[0] = ffma2(pp0A, cA0.x, accA[0]);
            accA[1] = ffma2(pp0A, cA0.y, accA[1]);
            accA[2] = ffma2(pp0A, cA1.x, accA[2]);
            accA[3] = ffma2(pp0A, cA1.y, accA[3]);
            accA[0] = ffma2(pp1A, cB0.x, accA[0]);
            accA[1] = ffma2(pp1A, cB0.y, accA[1]);
            accA[2] = ffma2(pp1A, cB1.x, accA[2]);
            accA[3] = ffma2(pp1A, cB1.y, accA[3]);
            accB[0] = ffma2(pp0B, cA0.x, accB[0]);
            accB[1] = ffma2(pp0B, cA0.y, accB[1]);
            accB[2] = ffma2(pp0B, cA1.x, accB[2]);
            accB[3] = ffma2(pp0B, cA1.y, accB[3]);
            accB[0] = ffma2(pp1B, cB0.x, accB[0]);
            accB[1] = ffma2(pp1B, cB0.y, accB[1]);
            accB[2] = ffma2(pp1B, cB1.x, accB[2]);
            accB[3] = ffma2(pp1B, cB1.y, accB[3]);
        }
    }

    // Write out: lane owns rows bbase+lane and bbase+lane+32 for its slice.
    const float inv_t = 1.0f / (float)TREES;
    float aA[CCLS], aB[CCLS];
#pragma unroll
    for (int qq = 0; qq < 4; qq++) {
        upk2(accA[qq], aA[2 * qq], aA[2 * qq + 1]);
        upk2(accB[qq], aB[2 * qq], aB[2 * qq + 1]);
    }
    float* orowA = out + (size_t)(bbase + lane) * CCLS;
    float* orowB = out + (size_t)(bbase + lane + 32) * CCLS;
#pragma unroll
    for (int c = 0; c < CCLS; c++) {
        atomicAdd(&orowA[c], aA[c] * inv_t);
        atomicAdd(&orowB[c], aB[c] * inv_t);
    }
}

// ---------------------------------------------------------------------------
extern "C" void kernel_launch(void* const* d_in, const int* in_sizes, int n_in,
                              void* d_out, int out_size)
{
    // Identify inputs by element count (order per metadata: input, W1, b1,
    // Bpos, Bneg, Cw — Bpos/Bneg are structurally fixed and unused).
    const float* x  = nullptr;
    const float* W1 = nullptr;
    const float* b1 = nullptr;
    const float* Cw = nullptr;
    for (int i = 0; i < n_in; i++) {
        switch (in_sizes[i]) {
            case BATCH * MFEAT:          x  = (const float*)d_in[i]; break; // 2097152
            case TREES * DNODES * MFEAT: W1 = (const float*)d_in[i]; break; // 8355840
            case TREES * DNODES:         b1 = (const float*)d_in[i]; break; // 16320
            case TREES * KLEAF * CCLS:   Cw = (const float*)d_in[i]; break; // 131072
            default: break;                                                 // Bpos/Bneg
        }
    }
    float* out = (float*)d_out;

    // xs + nd double buffer (2*256 float2) + Cw double buffer (2*512 float4).
    static const size_t smem_bytes =
        (size_t)(ROWS * XSTRIDE) * 4 + 2 * 256 * 8 + 2 * 512 * 16;   // ~148 KB
    cudaFuncSetAttribute(forest_kernel,
                         cudaFuncAttributeMaxDynamicSharedMemorySize,
                         (int)smem_bytes);

    cudaMemsetAsync(d_out, 0, (size_t)out_size * sizeof(float), 0);

    {
        int rows = TREES * DNODES;
        int warps_per_block = 8;
        int blocks = (rows + warps_per_block - 1) / warps_per_block;
        prep_kernel<<<blocks, warps_per_block * 32>>>(W1, b1);
    }

    dim3 grid(BATCH / ROWS, TREES / TGROUP);   // (64, 4) = 256 CTAs
    forest_kernel<<<grid, 512, smem_bytes>>>(x, Cw, out);
}

// round 12
// speedup vs baseline: 1.4717x; 1.0320x over previous
#include <cuda_runtime.h>
#include <cuda_bf16.h>
#include <cstdint>

// Problem constants (fixed by the dataset).
#define TREES 64
#define DNODES 255      // internal nodes per tree (2^8 - 1)
#define KLEAF 256       // leaves per tree
#define MFEAT 512       // features
#define CCLS 8          // classes
#define BATCH 4096

// Blocking: CTA = 512 threads (16 warps) over 64 batch rows x 16 trees.
// Lane L owns rows (bbase+L, bbase+L+32) -> f32x2-packed math.
// Warp: slice s = w&7 (leaves [32s,32s+32)), tree half h = w>>3.
// The two halves are fully decoupled after x staging (named barriers).
#define ROWS 64
#define TGROUP 16       // trees per CTA, split 8/8 across halves
#define XSTRIDE 513     // bank(L*513+f) = (L+f)%32; rows L and L+32 same sets -> conflict-free

#define ND_STRIDE 258   // float2 slots per nd buffer (node d stored at d+1 -> level starts 16B-aligned)

// Scratch (no cudaMalloc allowed): packed per-node parameters.
// g_node[t*DNODES+d] = { __int_as_float(feature_index), 5*b1 }.
__device__ float2 g_node[TREES * DNODES];

// ---------------------------------------------------------------------------
// Preprocess: extract one-hot feature index from W1 rows; pack with 5*b1.
// One warp per (t,d) row of 512 floats.
// ---------------------------------------------------------------------------
__global__ void prep_kernel(const float* __restrict__ W1,
                            const float* __restrict__ b1)
{
    int row = blockIdx.x * (blockDim.x >> 5) + (threadIdx.x >> 5);
    if (row >= TREES * DNODES) return;
    int lane = threadIdx.x & 31;

    const float4* w4 = reinterpret_cast<const float4*>(W1 + (size_t)row * MFEAT);
    int idx = 0;
#pragma unroll
    for (int i = 0; i < 4; i++) {
        float4 v = w4[i * 32 + lane];
        int base = (i * 32 + lane) * 4;
        if (v.x != 0.0f) idx = base + 0;
        if (v.y != 0.0f) idx = base + 1;
        if (v.z != 0.0f) idx = base + 2;
        if (v.w != 0.0f) idx = base + 3;
    }
#pragma unroll
    for (int off = 16; off; off >>= 1)
        idx = max(idx, __shfl_xor_sync(0xffffffffu, idx, off));
    if (lane == 0) {
        // sigmoid(10x+10b) = 0.5 + 0.5*tanh(5x+5b)
        g_node[row] = make_float2(__int_as_float(idx), 5.0f * b1[row]);
    }
}

// th = tanh(z) via single MUFU.TANH.
__device__ __forceinline__ float tanhf_hw(float z)
{
    float r;
    asm("tanh.approx.f32 %0, %1;" : "=f"(r) : "f"(z));
    return r;
}

typedef unsigned long long ull;

__device__ __forceinline__ ull pk2(float lo, float hi)
{
    ull r;
    asm("mov.b64 %0, {%1, %2};" : "=l"(r) : "f"(lo), "f"(hi));
    return r;
}
__device__ __forceinline__ ull ffma2(ull a, ull b, ull c)
{
    ull d;
    asm("fma.rn.f32x2 %0, %1, %2, %3;" : "=l"(d) : "l"(a), "l"(b), "l"(c));
    return d;
}
__device__ __forceinline__ ull mul2(ull a, ull b)
{
    ull d;
    asm("mul.rn.f32x2 %0, %1, %2;" : "=l"(d) : "l"(a), "l"(b));
    return d;
}
__device__ __forceinline__ void upk2(ull v, float& lo, float& hi)
{
    asm("mov.b64 {%0, %1}, %2;" : "=f"(lo), "=f"(hi) : "l"(v));
}

#define H2  0x3F0000003F000000ull   // {0.5f, 0.5f}
#define NH2 0xBF000000BF000000ull   // {-0.5f, -0.5f}

// Named barrier over one half's 256 threads.
__device__ __forceinline__ void barhalf(int h)
{
    asm volatile("bar.sync %0, 256;" :: "r"(h + 1) : "memory");
}

// ---------------------------------------------------------------------------
// Main kernel. 512 threads, 64 rows staged (row-major, stride 513). Two tree
// halves run fully decoupled (named barriers) with DOUBLE-BUFFERED nd/Cw
// tables: tree tt+1's tables are staged during tt's compute, hiding the L2
// latency. Level 4..7 node params are read as float4 pairs (aligned via +1
// node shift); level 7 evaluates 8 nodes before contracting (gather MLP=8).
// ---------------------------------------------------------------------------
__global__ __launch_bounds__(512, 1)
void forest_kernel(const float* __restrict__ x,
                   const float* __restrict__ Cw,
                   float* __restrict__ out)
{
    extern __shared__ float smem[];
    float*  xs   = smem;                                             // 64*513 floats
    float2* ndsh = reinterpret_cast<float2*>(smem + ROWS * XSTRIDE); // 4 * ND_STRIDE float2
    float4* cwsh = reinterpret_cast<float4*>(
        smem + ROWS * XSTRIDE + 2 * 4 * ND_STRIDE);                  // 4 * 512 float4

    const int tid   = threadIdx.x;
    const int lane  = tid & 31;
    const int w     = tid >> 5;
    const int s     = w & 7;          // leaf slice
    const int h     = w >> 3;         // tree half (also staging half: tid>>8)
    const int st    = tid & 255;      // index within half
    const int bbase = blockIdx.x * ROWS;
    const int tbase = blockIdx.y * TGROUP;

    // Stage 64 x-rows (coalesced LDG.128; scalar STS).
    {
        const float4* xg4 = reinterpret_cast<const float4*>(x + (size_t)bbase * MFEAT);
#pragma unroll
        for (int i = 0; i < (ROWS * MFEAT / 4) / 512; i++) {   // 16 iters
            int idx4 = i * 512 + tid;
            float4 v = xg4[idx4];
            int row = idx4 >> 7;              // 128 float4 per row
            int f   = (idx4 & 127) * 4;
            float* d = xs + row * XSTRIDE + f;
            d[0] = v.x; d[1] = v.y; d[2] = v.z; d[3] = v.w;
        }
    }

    // Stage one half-tree's tables into parity buffer par.
    auto stage = [&](int t_idx, int par) {
        if (t_idx < TGROUP / 2) {
            const int t_st = tbase + h * (TGROUP / 2) + t_idx;
            const float2* gsrc = g_node + (size_t)t_st * DNODES;
            float2* nddst = ndsh + (h * 2 + par) * ND_STRIDE + 1;   // node d -> slot d+1
            if (st < DNODES) nddst[st] = gsrc[st];
            const float4* cws = reinterpret_cast<const float4*>(
                Cw + (size_t)t_st * (KLEAF * CCLS));
            float4* cwd = cwsh + (h * 2 + par) * 512;
            cwd[st]       = cws[st];
            cwd[st + 256] = cws[st + 256];
        }
    };

    stage(0, 0);
    __syncthreads();    // xs globally staged + stage(0) complete

    // Warp-constant path node ids / sign splats (levels 0..2); level-3 = 7+s.
    const ull sg0 = (s & 4) ? H2 : NH2;
    const ull sg1 = (s & 2) ? H2 : NH2;
    const ull sg2 = (s & 1) ? H2 : NH2;
    const int a1 = 1 + (s >> 2);
    const int a2 = 3 + (s >> 1);
    const int a3 = 7 + s;

    const float* xrA = xs + lane * XSTRIDE;           // row bbase+lane
    const float* xrB = xs + (lane + 32) * XSTRIDE;    // row bbase+lane+32

    ull accA[4] = {0, 0, 0, 0};
    ull accB[4] = {0, 0, 0, 0};

    // Evaluate one node for both rows, pack as {rowA, rowB}.
    auto nodetf = [&](float fx, float tb) -> ull {
        int f = __float_as_int(fx);
        float tA = tanhf_hw(fmaf(5.0f, xrA[f], tb));
        float tB = tanhf_hw(fmaf(5.0f, xrB[f], tb));
        return pk2(tA, tB);
    };

#pragma unroll 1
    for (int tt = 0; tt < TGROUP / 2; tt++) {
        const int par = tt & 1;
        // Prefetch next tree's tables into the other parity (overlaps compute).
        stage(tt + 1, par ^ 1);

        const float2* ndf2 = ndsh + (h * 2 + par) * ND_STRIDE + 1;  // [node]
        const float4* nd4  = reinterpret_cast<const float4*>(
            ndsh + (h * 2 + par) * ND_STRIDE);                      // pair view
        const float4* cwh  = cwsh + (h * 2 + par) * 512;

        // Path levels 0..3 (scalar float2 broadcasts).
        float2 nv0 = ndf2[0], nv1 = ndf2[a1], nv2 = ndf2[a2], nv3 = ndf2[a3];
        ull th0 = nodetf(nv0.x, nv0.y);
        ull th1 = nodetf(nv1.x, nv1.y);
        ull th2 = nodetf(nv2.x, nv2.y);
        ull th3 = nodetf(nv3.x, nv3.y);
        ull pre = mul2(mul2(ffma2(sg0, th0, H2), ffma2(sg1, th1, H2)),
                       ffma2(sg2, th2, H2));
        ull pA = mul2(pre, ffma2(NH2, th3, H2));
        ull pB = mul2(pre, ffma2(H2,  th3, H2));

        // Level 4: nodes 15+2s, 16+2s -> one float4.
        ull q[4];
        {
            float4 v = nd4[8 + s];
            ull t4a = nodetf(v.x, v.y);
            ull t4b = nodetf(v.z, v.w);
            q[0] = mul2(pA, ffma2(NH2, t4a, H2)); q[1] = mul2(pA, ffma2(H2, t4a, H2));
            q[2] = mul2(pB, ffma2(NH2, t4b, H2)); q[3] = mul2(pB, ffma2(H2, t4b, H2));
        }
        // Level 5: nodes 31+4s .. 34+4s -> two float4.
        ull r[8];
#pragma unroll
        for (int j = 0; j < 2; j++) {
            float4 v = nd4[16 + 2 * s + j];
            ull ta = nodetf(v.x, v.y);
            ull tb = nodetf(v.z, v.w);
            r[4 * j + 0] = mul2(q[2 * j],     ffma2(NH2, ta, H2));
            r[4 * j + 1] = mul2(q[2 * j],     ffma2(H2,  ta, H2));
            r[4 * j + 2] = mul2(q[2 * j + 1], ffma2(NH2, tb, H2));
            r[4 * j + 3] = mul2(q[2 * j + 1], ffma2(H2,  tb, H2));
        }
        // Level 6: nodes 63+8s .. 70+8s -> four float4.
        ull u[16];
#pragma unroll
        for (int j = 0; j < 4; j++) {
            float4 v = nd4[32 + 4 * s + j];
            ull ta = nodetf(v.x, v.y);
            ull tb = nodetf(v.z, v.w);
            u[4 * j + 0] = mul2(r[2 * j],     ffma2(NH2, ta, H2));
            u[4 * j + 1] = mul2(r[2 * j],     ffma2(H2,  ta, H2));
            u[4 * j + 2] = mul2(r[2 * j + 1], ffma2(NH2, tb, H2));
            u[4 * j + 3] = mul2(r[2 * j + 1], ffma2(H2,  tb, H2));
        }

        // Level 7: nodes 127+16s .. 142+16s -> eight float4, in 2 batches of 8
        // nodes (gathers+tanh batched ahead of the contraction for MLP).
        const ulonglong2* cwp = reinterpret_cast<const ulonglong2*>(cwh) + (size_t)s * 64;
#pragma unroll
        for (int half7 = 0; half7 < 2; half7++) {
            ull th7[8];
#pragma unroll
            for (int j = 0; j < 4; j++) {
                float4 v = nd4[64 + 8 * s + 4 * half7 + j];
                th7[2 * j]     = nodetf(v.x, v.y);
                th7[2 * j + 1] = nodetf(v.z, v.w);
            }
#pragma unroll
            for (int jj = 0; jj < 8; jj++) {
                const int i = 8 * half7 + jj;      // level-7 node within slice
                ull th = th7[jj];
                ull P0 = mul2(u[i], ffma2(NH2, th, H2));
                ull P1 = mul2(u[i], ffma2(H2,  th, H2));
                float P0A, P0B, P1A, P1B;
                upk2(P0, P0A, P0B);
                upk2(P1, P1A, P1B);
                ulonglong2 cA0 = cwp[4 * i + 0];   // leaf 2i  : classes 0..3
                ulonglong2 cA1 = cwp[4 * i + 1];   // leaf 2i  : classes 4..7
                ulonglong2 cB0 = cwp[4 * i + 2];   // leaf 2i+1: classes 0..3
                ulonglong2 cB1 = cwp[4 * i + 3];   // leaf 2i+1: classes 4..7
                ull pp0A = pk2(P0A, P0A), pp1A = pk2(P1A, P1A);
                ull pp0B = pk2(P0B, P0B), pp1B = pk2(P1B, P1B);
                accA[0] = ffma2(pp0A, cA0.x, accA[0]);
                accA[1] = ffma2(pp0A, cA0.y, accA[1]);
                accA[2] = ffma2(pp0A, cA1.x, accA[2]);
                accA[3] = ffma2(pp0A, cA1.y, accA[3]);
                accA[0] = ffma2(pp1A, cB0.x, accA[0]);
                accA[1] = ffma2(pp1A, cB0.y, accA[1]);
                accA[2] = ffma2(pp1A, cB1.x, accA[2]);
                accA[3] = ffma2(pp1A, cB1.y, accA[3]);
                accB[0] = ffma2(pp0B, cA0.x, accB[0]);
                accB[1] = ffma2(pp0B, cA0.y, accB[1]);
                accB[2] = ffma2(pp0B, cA1.x, accB[2]);
                accB[3] = ffma2(pp0B, cA1.y, accB[3]);
                accB[0] = ffma2(pp1B, cB0.x, accB[0]);
                accB[1] = ffma2(pp1B, cB0.y, accB[1]);
                accB[2] = ffma2(pp1B, cB1.x, accB[2]);
                accB[3] = ffma2(pp1B, cB1.y, accB[3]);
            }
        }

        barhalf(h);   // stage(tt+1) complete; parity par free for tt+2
    }

    // Write out: lane owns rows bbase+lane and bbase+lane+32 for its slice.
    const float inv_t = 1.0f / (float)TREES;
    float aA[CCLS], aB[CCLS];
#pragma unroll
    for (int qq = 0; qq < 4; qq++) {
        upk2(accA[qq], aA[2 * qq], aA[2 * qq + 1]);
        upk2(accB[qq], aB[2 * qq], aB[2 * qq + 1]);
    }
    float* orowA = out + (size_t)(bbase + lane) * CCLS;
    float* orowB = out + (size_t)(bbase + lane + 32) * CCLS;
#pragma unroll
    for (int c = 0; c < CCLS; c++) {
        atomicAdd(&orowA[c], aA[c] * inv_t);
        atomicAdd(&orowB[c], aB[c] * inv_t);
    }
}

// ---------------------------------------------------------------------------
extern "C" void kernel_launch(void* const* d_in, const int* in_sizes, int n_in,
                              void* d_out, int out_size)
{
    // Identify inputs by element count (order per metadata: input, W1, b1,
    // Bpos, Bneg, Cw — Bpos/Bneg are structurally fixed and unused).
    const float* x  = nullptr;
    const float* W1 = nullptr;
    const float* b1 = nullptr;
    const float* Cw = nullptr;
    for (int i = 0; i < n_in; i++) {
        switch (in_sizes[i]) {
            case BATCH * MFEAT:          x  = (const float*)d_in[i]; break; // 2097152
            case TREES * DNODES * MFEAT: W1 = (const float*)d_in[i]; break; // 8355840
            case TREES * DNODES:         b1 = (const float*)d_in[i]; break; // 16320
            case TREES * KLEAF * CCLS:   Cw = (const float*)d_in[i]; break; // 131072
            default: break;                                                 // Bpos/Bneg
        }
    }
    float* out = (float*)d_out;

    // xs + nd 4 buffers (4*ND_STRIDE float2) + Cw 4 buffers (4*512 float4).
    static const size_t smem_bytes =
        (size_t)(ROWS * XSTRIDE) * 4 + 4 * ND_STRIDE * 8 + 4 * 512 * 16;  // ~168 KB
    cudaFuncSetAttribute(forest_kernel,
                         cudaFuncAttributeMaxDynamicSharedMemorySize,
                         (int)smem_bytes);

    cudaMemsetAsync(d_out, 0, (size_t)out_size * sizeof(float), 0);

    {
        int rows = TREES * DNODES;
        int warps_per_block = 8;
        int blocks = (rows + warps_per_block - 1) / warps_per_block;
        prep_kernel<<<blocks, warps_per_block * 32>>>(W1, b1);
    }

    dim3 grid(BATCH / ROWS, TREES / TGROUP);   // (64, 4) = 256 CTAs
    forest_kernel<<<grid, 512, smem_bytes>>>(x, Cw, out);
}